// round 3
// baseline (speedup 1.0000x reference)
#include <cuda_runtime.h>
#include <cuda_bf16.h>
#include <cstdint>

// ============================================================================
// ConvolutionFromEdgeSetUpdate:
//   messages = relu([node[src] | node[tgt] | edge] @ W + b)   (E x 64)
//   out      = segment_sum(messages, tgt, 50000)
// E=800000, D=64, U=64, K=192.
//
// R3: HMMA bf16 3-product split (rel_err ~3e-6), now with
//  - 2 CTAs/SM (128 thr, TILE_M=64) for gather<->MMA overlap
//  - coalesced gather (16 threads x 16B per row)
//  - (2 m-blk x 4 n-blk) warp tile + paired ldsm_x4 for B
// ============================================================================

#define NN_NODES 50000
#define NN_EDGES 800000
#define D_FEAT   64
#define UNITS    64
#define KDIM     192
#define TILE_M   64
#define N_TILES  (NN_EDGES / TILE_M)   // 12500
#define THREADS  128                   // 4 warps: 2 m-groups x 2 n-groups
#define GRID_X   296                   // 2 CTAs per SM

// SMEM: row-major bf16, row stride 200 bf16 = 400 B
// (16B-aligned; 400 mod 128 = 16 -> ldmatrix row sets conflict-free)
#define STRIDE_B   400
#define SM_A_HI    0
#define SM_A_LO    (SM_A_HI + TILE_M * STRIDE_B)     // 25600
#define SM_B_HI    (SM_A_LO + TILE_M * STRIDE_B)     // 51200
#define SM_B_LO    (SM_B_HI + UNITS * STRIDE_B)      // 76800
#define SM_TOTAL   (SM_B_LO + UNITS * STRIDE_B)      // 102400 -> 2 CTAs/SM

// ---------------- helpers ----------------

__device__ __forceinline__ uint32_t smem_to_u32(const void* smem_ptr) {
    uint32_t addr;
    asm("{ .reg .u64 tmp; cvta.to.shared.u64 tmp, %1; cvt.u32.u64 %0, tmp; }"
        : "=r"(addr) : "l"(smem_ptr));
    return addr;
}

__device__ __forceinline__ void ldsm_x4(uint32_t* r, uint32_t addr) {
    asm volatile("ldmatrix.sync.aligned.m8n8.x4.shared.b16 {%0,%1,%2,%3}, [%4];"
        : "=r"(r[0]), "=r"(r[1]), "=r"(r[2]), "=r"(r[3]) : "r"(addr));
}

__device__ __forceinline__ void mma_bf16(float* c, const uint32_t* a, const uint32_t* b) {
    asm volatile(
        "mma.sync.aligned.m16n8k16.row.col.f32.bf16.bf16.f32 "
        "{%0,%1,%2,%3}, {%4,%5,%6,%7}, {%8,%9}, {%0,%1,%2,%3};"
        : "+f"(c[0]), "+f"(c[1]), "+f"(c[2]), "+f"(c[3])
        : "r"(a[0]), "r"(a[1]), "r"(a[2]), "r"(a[3]), "r"(b[0]), "r"(b[1]));
}

__device__ __forceinline__ uint32_t pack_bf16x2(float a, float b) {
    __nv_bfloat162 t = __halves2bfloat162(__float2bfloat16(a), __float2bfloat16(b));
    return *reinterpret_cast<uint32_t*>(&t);
}

__device__ __forceinline__ void split2(float x, float& hi_f, float& lo_f) {
    __nv_bfloat16 h = __float2bfloat16(x);
    hi_f = __bfloat162float(h);
    lo_f = x - hi_f;
}

// ---------------- zero output (d_out is poisoned 0xAA) ----------------

__global__ void zero_out_kernel(float4* out) {
    int i = blockIdx.x * blockDim.x + threadIdx.x;
    if (i < NN_NODES * UNITS / 4) out[i] = make_float4(0.f, 0.f, 0.f, 0.f);
}

// ---------------- main fused kernel ----------------

__global__ __launch_bounds__(THREADS, 2)
void edgeconv_kernel(const float* __restrict__ node_feat,
                     const float* __restrict__ edge_feat,
                     const int*   __restrict__ src_idx,
                     const int*   __restrict__ tgt_idx,
                     const float* __restrict__ W,
                     const float* __restrict__ bias,
                     float*       __restrict__ out)
{
    extern __shared__ char smem[];
    const uint32_t smem_base = smem_to_u32(smem);
    const int tid  = threadIdx.x;
    const int wid  = tid >> 5;
    const int lane = tid & 31;

    // ---- build B = W^T hi/lo in SMEM: Bsm[n][k], k contiguous ----
    for (int task = tid; task < 192; task += THREADS) {
        const int n = task & 63, bseg = task >> 6;
        char* rowp_hi = smem + SM_B_HI + n * STRIDE_B;
        char* rowp_lo = smem + SM_B_LO + n * STRIDE_B;
        #pragma unroll 8
        for (int j = 0; j < 64; ++j) {
            const int k = bseg * 64 + j;
            float x = W[k * UNITS + n];
            float hf, lf; split2(x, hf, lf);
            *reinterpret_cast<__nv_bfloat16*>(rowp_hi + k * 2) = __float2bfloat16(hf);
            *reinterpret_cast<__nv_bfloat16*>(rowp_lo + k * 2) = __float2bfloat16(lf);
        }
    }

    // warp tile: mg in {0,1} picks 32 rows, ng in {0,1} picks 32 cols
    const int mg = wid >> 1;
    const int ng = wid & 1;
    const int t4 = lane & 3;        // col pair within n-block
    const int g  = lane >> 2;       // row within 8-row group

    // per-thread bias: cols ng*32 + nb*8 + 2*t4 + {0,1}
    float bj0[4], bj1[4];
    #pragma unroll
    for (int nb = 0; nb < 4; ++nb) {
        bj0[nb] = bias[ng * 32 + nb * 8 + 2 * t4];
        bj1[nb] = bias[ng * 32 + nb * 8 + 2 * t4 + 1];
    }

    // ldmatrix lane offsets
    // A (16x16 x4): lanes 0-15 -> rows @k0, 16-31 -> rows @k0+8 elems (16B)
    const uint32_t a_lane_off =
        (uint32_t)((mg * 32 + (lane & 15)) * STRIDE_B + (lane >> 4) * 16);
    // B paired (two 8-row n-blocks per x4):
    // lanes 0-7: rows nb0 @k0 | 8-15: rows nb0 @k0+8 | 16-23: nb0+8 rows @k0 | 24-31: @k0+8
    const int brow_sel = (lane & 7) + ((lane >> 4) << 3);
    const uint32_t b_lane_off =
        (uint32_t)((ng * 32 + brow_sel) * STRIDE_B + ((lane >> 3) & 1) * 16);

    const uint32_t aHI = smem_base + SM_A_HI + a_lane_off;
    const uint32_t aLO = smem_base + SM_A_LO + a_lane_off;
    const uint32_t bHI = smem_base + SM_B_HI + b_lane_off;
    const uint32_t bLO = smem_base + SM_B_LO + b_lane_off;

    // gather mapping: 16 threads per (row,seg), 16B chunk each
    const int g_chunk = tid & 15;          // float4 index within 64-float row
    const int g_rs0   = tid >> 4;          // first rowseg (0..7), step 8

    __syncthreads();   // B tiles ready

    for (int tile = blockIdx.x; tile < N_TILES; tile += GRID_X) {
        // ============ gather + convert A tile (hi/lo), coalesced ============
        // rowsegs: 0..63 = src rows, 64..127 = tgt rows, 128..191 = edge rows
        #pragma unroll 4
        for (int rs = g_rs0; rs < 3 * TILE_M; rs += THREADS / 16) {
            const int row = rs & (TILE_M - 1);
            const int seg = rs >> 6;               // 0,1,2
            const int e   = tile * TILE_M + row;
            const float* p;
            if (seg == 0)      p = node_feat + (size_t)__ldg(src_idx + e) * D_FEAT;
            else if (seg == 1) p = node_feat + (size_t)__ldg(tgt_idx + e) * D_FEAT;
            else               p = edge_feat + (size_t)e * D_FEAT;
            float4 v = __ldg(reinterpret_cast<const float4*>(p) + g_chunk);
            float h0,l0,h1,l1,h2,l2,h3,l3;
            split2(v.x, h0, l0); split2(v.y, h1, l1);
            split2(v.z, h2, l2); split2(v.w, h3, l3);
            uint2 hh; hh.x = pack_bf16x2(h0, h1); hh.y = pack_bf16x2(h2, h3);
            uint2 ll; ll.x = pack_bf16x2(l0, l1); ll.y = pack_bf16x2(l2, l3);
            const uint32_t off = (uint32_t)(row * STRIDE_B + seg * 128 + g_chunk * 8);
            *reinterpret_cast<uint2*>(smem + SM_A_HI + off) = hh;
            *reinterpret_cast<uint2*>(smem + SM_A_LO + off) = ll;
        }
        __syncthreads();

        // ============ MMA: warp = 32 rows x 32 cols, K=192 ============
        float acc[2][4][4];
        #pragma unroll
        for (int mb = 0; mb < 2; ++mb)
            #pragma unroll
            for (int nb = 0; nb < 4; ++nb)
                #pragma unroll
                for (int q = 0; q < 4; ++q) acc[mb][nb][q] = 0.f;

        #pragma unroll
        for (int ks = 0; ks < KDIM / 16; ++ks) {   // 12 k-steps
            const uint32_t kb = (uint32_t)(ks * 32);
            uint32_t ahi[2][4], alo[2][4];
            ldsm_x4(ahi[0], aHI + kb);
            ldsm_x4(ahi[1], aHI + kb + 16 * STRIDE_B);
            ldsm_x4(alo[0], aLO + kb);
            ldsm_x4(alo[1], aLO + kb + 16 * STRIDE_B);
            uint32_t bhi[4][2], blo[4][2];   // [nb][2]
            {
                uint32_t r[4];
                ldsm_x4(r, bHI + kb);                      // nb 0,1
                bhi[0][0]=r[0]; bhi[0][1]=r[1]; bhi[1][0]=r[2]; bhi[1][1]=r[3];
                ldsm_x4(r, bHI + kb + 16 * STRIDE_B);      // nb 2,3
                bhi[2][0]=r[0]; bhi[2][1]=r[1]; bhi[3][0]=r[2]; bhi[3][1]=r[3];
                ldsm_x4(r, bLO + kb);
                blo[0][0]=r[0]; blo[0][1]=r[1]; blo[1][0]=r[2]; blo[1][1]=r[3];
                ldsm_x4(r, bLO + kb + 16 * STRIDE_B);
                blo[2][0]=r[0]; blo[2][1]=r[1]; blo[3][0]=r[2]; blo[3][1]=r[3];
            }
            #pragma unroll
            for (int mb = 0; mb < 2; ++mb) {
                #pragma unroll
                for (int nb = 0; nb < 4; ++nb) {
                    mma_bf16(acc[mb][nb], ahi[mb], bhi[nb]);
                    mma_bf16(acc[mb][nb], ahi[mb], blo[nb]);
                    mma_bf16(acc[mb][nb], alo[mb], bhi[nb]);
                }
            }
        }
        __syncthreads();   // A tile free for next gather

        // ============ epilogue: bias + relu + red.v2 scatter ============
        #pragma unroll
        for (int mb = 0; mb < 2; ++mb) {
            const int e0 = tile * TILE_M + mg * 32 + mb * 16 + g;
            const int e1 = e0 + 8;
            float* o0 = out + (size_t)__ldg(tgt_idx + e0) * UNITS + ng * 32 + 2 * t4;
            float* o1 = out + (size_t)__ldg(tgt_idx + e1) * UNITS + ng * 32 + 2 * t4;
            #pragma unroll
            for (int nb = 0; nb < 4; ++nb) {
                float v0 = fmaxf(acc[mb][nb][0] + bj0[nb], 0.f);
                float v1 = fmaxf(acc[mb][nb][1] + bj1[nb], 0.f);
                float v2 = fmaxf(acc[mb][nb][2] + bj0[nb], 0.f);
                float v3 = fmaxf(acc[mb][nb][3] + bj1[nb], 0.f);
                asm volatile("red.global.add.v2.f32 [%0], {%1, %2};"
                             :: "l"(o0 + nb * 8), "f"(v0), "f"(v1) : "memory");
                asm volatile("red.global.add.v2.f32 [%0], {%1, %2};"
                             :: "l"(o1 + nb * 8), "f"(v2), "f"(v3) : "memory");
            }
        }
    }
}

// ---------------- launch ----------------

extern "C" void kernel_launch(void* const* d_in, const int* in_sizes, int n_in,
                              void* d_out, int out_size) {
    const float* node_feat = (const float*)d_in[0];
    const float* edge_feat = (const float*)d_in[1];
    const int*   src_idx   = (const int*)d_in[2];
    const int*   tgt_idx   = (const int*)d_in[3];
    const float* W         = (const float*)d_in[4];
    const float* b         = (const float*)d_in[5];
    float* out = (float*)d_out;

    int n4 = NN_NODES * UNITS / 4;
    zero_out_kernel<<<(n4 + 255) / 256, 256>>>((float4*)out);

    static int configured = 0;
    if (!configured) {
        cudaFuncSetAttribute(edgeconv_kernel,
                             cudaFuncAttributeMaxDynamicSharedMemorySize, SM_TOTAL);
        configured = 1;
    }
    edgeconv_kernel<<<GRID_X, THREADS, SM_TOTAL>>>(
        node_feat, edge_feat, src_idx, tgt_idx, W, b, out);
}

// round 4
// speedup vs baseline: 1.1603x; 1.1603x over previous
#include <cuda_runtime.h>
#include <cuda_bf16.h>
#include <cstdint>

// ============================================================================
// ConvolutionFromEdgeSetUpdate:
//   messages = relu([node[src] | node[tgt] | edge] @ W + b)   (E x 64)
//   out      = segment_sum(messages, tgt, 50000)
// E=800000, D=64, U=64, K=192.
//
// R4: back to R2 skeleton (148 CTAs x 256 thr, TILE_M=128, 1 CTA/SM) plus:
//  - warp tile 32x32 (4m x 2n) -> B-ldsm traffic halved vs R2
//  - shuffle-combined red.global.add.v4 epilogue (half the atomic ops)
//  - double-buffered SMEM-staged indices, staged under the MMA phase
// ============================================================================

#define NN_NODES 50000
#define NN_EDGES 800000
#define D_FEAT   64
#define UNITS    64
#define KDIM     192
#define TILE_M   128
#define N_TILES  (NN_EDGES / TILE_M)   // 6250
#define THREADS  256                   // 8 warps: 4 m-groups x 2 n-groups
#define GRID_X   148

// SMEM: row-major bf16, row stride 200 bf16 = 400 B
// (16B-aligned; 400 mod 128 = 16 -> ldmatrix row sets conflict-free)
#define STRIDE_B   400
#define SM_A_HI    0
#define SM_A_LO    (SM_A_HI + TILE_M * STRIDE_B)     // 51200
#define SM_B_HI    (SM_A_LO + TILE_M * STRIDE_B)     // 102400
#define SM_B_LO    (SM_B_HI + UNITS * STRIDE_B)      // 128000
#define SM_IDX     (SM_B_LO + UNITS * STRIDE_B)      // 153600: 2 bufs x 256 int
#define SM_TOTAL   (SM_IDX + 2 * 256 * 4)            // 155648

// ---------------- helpers ----------------

__device__ __forceinline__ uint32_t smem_to_u32(const void* smem_ptr) {
    uint32_t addr;
    asm("{ .reg .u64 tmp; cvta.to.shared.u64 tmp, %1; cvt.u32.u64 %0, tmp; }"
        : "=r"(addr) : "l"(smem_ptr));
    return addr;
}

__device__ __forceinline__ void ldsm_x4(uint32_t* r, uint32_t addr) {
    asm volatile("ldmatrix.sync.aligned.m8n8.x4.shared.b16 {%0,%1,%2,%3}, [%4];"
        : "=r"(r[0]), "=r"(r[1]), "=r"(r[2]), "=r"(r[3]) : "r"(addr));
}

__device__ __forceinline__ void mma_bf16(float* c, const uint32_t* a, const uint32_t* b) {
    asm volatile(
        "mma.sync.aligned.m16n8k16.row.col.f32.bf16.bf16.f32 "
        "{%0,%1,%2,%3}, {%4,%5,%6,%7}, {%8,%9}, {%0,%1,%2,%3};"
        : "+f"(c[0]), "+f"(c[1]), "+f"(c[2]), "+f"(c[3])
        : "r"(a[0]), "r"(a[1]), "r"(a[2]), "r"(a[3]), "r"(b[0]), "r"(b[1]));
}

__device__ __forceinline__ uint32_t pack_bf16x2(float a, float b) {
    __nv_bfloat162 t = __halves2bfloat162(__float2bfloat16(a), __float2bfloat16(b));
    return *reinterpret_cast<uint32_t*>(&t);
}

__device__ __forceinline__ void split2(float x, float& hi_f, float& lo_f) {
    __nv_bfloat16 h = __float2bfloat16(x);
    hi_f = __bfloat162float(h);
    lo_f = x - hi_f;
}

// ---------------- zero output (d_out is poisoned 0xAA) ----------------

__global__ void zero_out_kernel(float4* out) {
    int i = blockIdx.x * blockDim.x + threadIdx.x;
    if (i < NN_NODES * UNITS / 4) out[i] = make_float4(0.f, 0.f, 0.f, 0.f);
}

// ---------------- main fused kernel ----------------

__global__ __launch_bounds__(THREADS, 1)
void edgeconv_kernel(const float* __restrict__ node_feat,
                     const float* __restrict__ edge_feat,
                     const int*   __restrict__ src_idx,
                     const int*   __restrict__ tgt_idx,
                     const float* __restrict__ W,
                     const float* __restrict__ bias,
                     float*       __restrict__ out)
{
    extern __shared__ char smem[];
    const uint32_t smem_base = smem_to_u32(smem);
    const int tid  = threadIdx.x;
    const int wid  = tid >> 5;
    const int lane = tid & 31;

    int* const idx_sm = reinterpret_cast<int*>(smem + SM_IDX);

    // ---- build B = W^T hi/lo in SMEM: Bsm[n][k], k contiguous ----
    for (int task = tid; task < 192; task += THREADS) {
        const int n = task & 63, bseg = task >> 6;
        char* rowp_hi = smem + SM_B_HI + n * STRIDE_B;
        char* rowp_lo = smem + SM_B_LO + n * STRIDE_B;
        #pragma unroll 8
        for (int j = 0; j < 64; ++j) {
            const int k = bseg * 64 + j;
            float x = W[k * UNITS + n];
            float hf, lf; split2(x, hf, lf);
            *reinterpret_cast<__nv_bfloat16*>(rowp_hi + k * 2) = __float2bfloat16(hf);
            *reinterpret_cast<__nv_bfloat16*>(rowp_lo + k * 2) = __float2bfloat16(lf);
        }
    }

    // ---- stage indices for the first tile into buffer 0 ----
    {
        const int t0 = blockIdx.x;
        const int e  = t0 * TILE_M + (tid & 127);
        idx_sm[tid] = (tid < 128) ? __ldg(src_idx + e) : __ldg(tgt_idx + e);
    }

    // warp tile: mg in {0..3} picks 32 rows, ng in {0,1} picks 32 cols
    const int mg = wid >> 1;
    const int ng = wid & 1;
    const int t4 = lane & 3;
    const int g  = lane >> 2;

    // per-thread bias: cols ng*32 + nb*8 + 2*t4 + {0,1}
    float bj0[4], bj1[4];
    #pragma unroll
    for (int nb = 0; nb < 4; ++nb) {
        bj0[nb] = bias[ng * 32 + nb * 8 + 2 * t4];
        bj1[nb] = bias[ng * 32 + nb * 8 + 2 * t4 + 1];
    }

    // ldmatrix lane offsets
    const uint32_t a_lane_off =
        (uint32_t)((mg * 32 + (lane & 15)) * STRIDE_B + (lane >> 4) * 16);
    const int brow_sel = (lane & 7) + ((lane >> 4) << 3);
    const uint32_t b_lane_off =
        (uint32_t)((ng * 32 + brow_sel) * STRIDE_B + ((lane >> 3) & 1) * 16);

    const uint32_t aHI = smem_base + SM_A_HI + a_lane_off;
    const uint32_t aLO = smem_base + SM_A_LO + a_lane_off;
    const uint32_t bHI = smem_base + SM_B_HI + b_lane_off;
    const uint32_t bLO = smem_base + SM_B_LO + b_lane_off;

    // gather mapping: 16 threads per (row,seg), one 16B chunk each
    const int g_chunk = tid & 15;          // float4 index within 64-float row
    const int g_rs0   = tid >> 4;          // first rowseg (0..15), step 16

    const bool epi_even = (t4 & 1) == 0;
    const int  epi_coloff = ng * 32 + 2 * (t4 & ~1);

    __syncthreads();   // B tiles + idx buf0 ready

    int pb = 0;
    for (int tile = blockIdx.x; tile < N_TILES; tile += GRID_X) {
        const int* idxp = idx_sm + pb * 256;

        // ============ gather + convert A tile (hi/lo), coalesced ============
        // rowsegs: 0..127 src rows, 128..255 tgt rows, 256..383 edge rows
        #pragma unroll 4
        for (int rs = g_rs0; rs < 3 * TILE_M; rs += THREADS / 16) {
            const int row = rs & (TILE_M - 1);
            const int seg = rs >> 7;               // 0,1,2
            const float* p;
            if (seg == 2) p = edge_feat + (size_t)(tile * TILE_M + row) * D_FEAT;
            else          p = node_feat + (size_t)idxp[rs] * D_FEAT;
            float4 v = __ldg(reinterpret_cast<const float4*>(p) + g_chunk);
            float h0,l0,h1,l1,h2,l2,h3,l3;
            split2(v.x, h0, l0); split2(v.y, h1, l1);
            split2(v.z, h2, l2); split2(v.w, h3, l3);
            uint2 hh; hh.x = pack_bf16x2(h0, h1); hh.y = pack_bf16x2(h2, h3);
            uint2 ll; ll.x = pack_bf16x2(l0, l1); ll.y = pack_bf16x2(l2, l3);
            const uint32_t off = (uint32_t)(row * STRIDE_B + seg * 128 + g_chunk * 8);
            *reinterpret_cast<uint2*>(smem + SM_A_HI + off) = hh;
            *reinterpret_cast<uint2*>(smem + SM_A_LO + off) = ll;
        }
        __syncthreads();

        // ---- stage next tile's indices (LDG latency hides under MMA) ----
        {
            const int nxt = tile + GRID_X;
            if (nxt < N_TILES) {
                const int e = nxt * TILE_M + (tid & 127);
                idx_sm[(pb ^ 1) * 256 + tid] =
                    (tid < 128) ? __ldg(src_idx + e) : __ldg(tgt_idx + e);
            }
        }

        // ============ MMA: warp = 32 rows x 32 cols, K=192 ============
        float acc[2][4][4];
        #pragma unroll
        for (int mb = 0; mb < 2; ++mb)
            #pragma unroll
            for (int nb = 0; nb < 4; ++nb)
                #pragma unroll
                for (int q = 0; q < 4; ++q) acc[mb][nb][q] = 0.f;

        #pragma unroll
        for (int ks = 0; ks < KDIM / 16; ++ks) {   // 12 k-steps
            const uint32_t kb = (uint32_t)(ks * 32);
            uint32_t ahi[2][4], alo[2][4];
            ldsm_x4(ahi[0], aHI + kb);
            ldsm_x4(ahi[1], aHI + kb + 16 * STRIDE_B);
            ldsm_x4(alo[0], aLO + kb);
            ldsm_x4(alo[1], aLO + kb + 16 * STRIDE_B);
            uint32_t bhi[4][2], blo[4][2];
            {
                uint32_t r[4];
                ldsm_x4(r, bHI + kb);                  // nb 0,1
                bhi[0][0]=r[0]; bhi[0][1]=r[1]; bhi[1][0]=r[2]; bhi[1][1]=r[3];
                ldsm_x4(r, bHI + kb + 16 * STRIDE_B);  // nb 2,3
                bhi[2][0]=r[0]; bhi[2][1]=r[1]; bhi[3][0]=r[2]; bhi[3][1]=r[3];
                ldsm_x4(r, bLO + kb);
                blo[0][0]=r[0]; blo[0][1]=r[1]; blo[1][0]=r[2]; blo[1][1]=r[3];
                ldsm_x4(r, bLO + kb + 16 * STRIDE_B);
                blo[2][0]=r[0]; blo[2][1]=r[1]; blo[3][0]=r[2]; blo[3][1]=r[3];
            }
            #pragma unroll
            for (int mb = 0; mb < 2; ++mb) {
                #pragma unroll
                for (int nb = 0; nb < 4; ++nb) {
                    mma_bf16(acc[mb][nb], ahi[mb], bhi[nb]);
                    mma_bf16(acc[mb][nb], ahi[mb], blo[nb]);
                    mma_bf16(acc[mb][nb], alo[mb], bhi[nb]);
                }
            }
        }

        // ============ epilogue: bias+relu, lane^1 combine, red.v4 ============
        #pragma unroll
        for (int mb = 0; mb < 2; ++mb) {
            #pragma unroll
            for (int nb = 0; nb < 4; ++nb) {
                float v0 = fmaxf(acc[mb][nb][0] + bj0[nb], 0.f);
                float v1 = fmaxf(acc[mb][nb][1] + bj1[nb], 0.f);
                float v2 = fmaxf(acc[mb][nb][2] + bj0[nb], 0.f);
                float v3 = fmaxf(acc[mb][nb][3] + bj1[nb], 0.f);
                // exchange with column-pair partner (lane ^ 1, same row group)
                float e0 = __shfl_xor_sync(0xFFFFFFFFu, v0, 1);
                float e1 = __shfl_xor_sync(0xFFFFFFFFu, v1, 1);
                float e2 = __shfl_xor_sync(0xFFFFFFFFu, v2, 1);
                float e3 = __shfl_xor_sync(0xFFFFFFFFu, v3, 1);
                // even t4 -> row g (v0,v1 | partner v0,v1)
                // odd  t4 -> row g+8 (partner v2,v3 | v2,v3)
                float f0 = epi_even ? v0 : e2;
                float f1 = epi_even ? v1 : e3;
                float f2 = epi_even ? e0 : v2;
                float f3 = epi_even ? e1 : v3;
                const int rloc = mg * 32 + mb * 16 + g + (epi_even ? 0 : 8);
                const int tgt  = idxp[128 + rloc];
                float* o = out + (size_t)tgt * UNITS + epi_coloff + nb * 8;
                asm volatile("red.global.add.v4.f32 [%0], {%1, %2, %3, %4};"
                             :: "l"(o), "f"(f0), "f"(f1), "f"(f2), "f"(f3)
                             : "memory");
            }
        }
        __syncthreads();   // A tile + idx bufs consistent for next iteration
        pb ^= 1;
    }
}

// ---------------- launch ----------------

extern "C" void kernel_launch(void* const* d_in, const int* in_sizes, int n_in,
                              void* d_out, int out_size) {
    const float* node_feat = (const float*)d_in[0];
    const float* edge_feat = (const float*)d_in[1];
    const int*   src_idx   = (const int*)d_in[2];
    const int*   tgt_idx   = (const int*)d_in[3];
    const float* W         = (const float*)d_in[4];
    const float* b         = (const float*)d_in[5];
    float* out = (float*)d_out;

    int n4 = NN_NODES * UNITS / 4;
    zero_out_kernel<<<(n4 + 255) / 256, 256>>>((float4*)out);

    static int configured = 0;
    if (!configured) {
        cudaFuncSetAttribute(edgeconv_kernel,
                             cudaFuncAttributeMaxDynamicSharedMemorySize, SM_TOTAL);
        configured = 1;
    }
    edgeconv_kernel<<<GRID_X, THREADS, SM_TOTAL>>>(
        node_feat, edge_feat, src_idx, tgt_idx, W, b, out);
}